// round 1
// baseline (speedup 1.0000x reference)
#include <cuda_runtime.h>
#include <cuda_bf16.h>

#define N_USERS  100000
#define N_ITEMS  200000
#define N_NODES  300000
#define NNZ      9600000
#define DIM      64
#define TOTAL_F  (N_NODES * DIM)          // 19,200,000 floats
#define TOTAL_V4 (TOTAL_F / 4)            // 4,800,000 float4
#define USER_V4  (N_USERS * DIM / 4)      // 1,600,000 float4

// Ping-pong embedding buffers (alloc-free rule: __device__ globals)
__device__ float g_bufA[(size_t)TOTAL_F];
__device__ float g_bufB[(size_t)TOTAL_F];

// ---------------------------------------------------------------------------
// init: bufA = concat(user, item); out = 0.25*bufA; bufB = 0
// ---------------------------------------------------------------------------
__global__ void init_kernel(const float4* __restrict__ user,
                            const float4* __restrict__ item,
                            float4* __restrict__ out) {
    int i = blockIdx.x * blockDim.x + threadIdx.x;
    if (i >= TOTAL_V4) return;
    float4 v = (i < USER_V4) ? __ldg(&user[i]) : __ldg(&item[i - USER_V4]);
    float4* a = reinterpret_cast<float4*>(g_bufA);
    float4* b = reinterpret_cast<float4*>(g_bufB);
    a[i] = v;
    out[i] = make_float4(0.25f * v.x, 0.25f * v.y, 0.25f * v.z, 0.25f * v.w);
    b[i] = make_float4(0.f, 0.f, 0.f, 0.f);
}

// ---------------------------------------------------------------------------
// SpMM: y[rows[e]] += vals[e] * x[cols[e]]   (16 threads per edge, float4)
// NNZ = 9,600,000 = 600,000 blocks * 16 edges/block exactly (no tail).
// ---------------------------------------------------------------------------
__global__ void __launch_bounds__(256)
spmm_kernel(const int*   __restrict__ rows,
            const int*   __restrict__ cols,
            const float* __restrict__ vals,
            const float* __restrict__ x,
            float*       __restrict__ y) {
    int t = blockIdx.x * blockDim.x + threadIdx.x;
    int e = t >> 4;          // edge index
    int c = t & 15;          // float4 chunk within the 64-dim row
    int r   = __ldg(&rows[e]);
    int col = __ldg(&cols[e]);
    float v = __ldg(&vals[e]);

    const float4* xp = reinterpret_cast<const float4*>(x + (size_t)col * DIM) + c;
    float4 xv = __ldg(xp);
    float4 m  = make_float4(v * xv.x, v * xv.y, v * xv.z, v * xv.w);

    float* dst = y + (size_t)r * DIM + (size_t)c * 4;
    asm volatile("red.global.add.v4.f32 [%0], {%1, %2, %3, %4};"
                 :: "l"(dst), "f"(m.x), "f"(m.y), "f"(m.z), "f"(m.w)
                 : "memory");
}

// ---------------------------------------------------------------------------
// accumulate: out += 0.25 * src;  and zero the OTHER ping-pong buffer
// ---------------------------------------------------------------------------
__global__ void acc_zero_kernel(float4* __restrict__ out,
                                const float4* __restrict__ src,
                                float4* __restrict__ zbuf) {
    int i = blockIdx.x * blockDim.x + threadIdx.x;
    if (i >= TOTAL_V4) return;
    float4 s = __ldg(&src[i]);
    float4 o = out[i];
    o.x += 0.25f * s.x; o.y += 0.25f * s.y;
    o.z += 0.25f * s.z; o.w += 0.25f * s.w;
    out[i]  = o;
    zbuf[i] = make_float4(0.f, 0.f, 0.f, 0.f);
}

__global__ void acc_final_kernel(float4* __restrict__ out,
                                 const float4* __restrict__ src) {
    int i = blockIdx.x * blockDim.x + threadIdx.x;
    if (i >= TOTAL_V4) return;
    float4 s = __ldg(&src[i]);
    float4 o = out[i];
    o.x += 0.25f * s.x; o.y += 0.25f * s.y;
    o.z += 0.25f * s.z; o.w += 0.25f * s.w;
    out[i] = o;
}

// ---------------------------------------------------------------------------
extern "C" void kernel_launch(void* const* d_in, const int* in_sizes, int n_in,
                              void* d_out, int out_size) {
    const int*   rows = (const int*)  d_in[0];
    const int*   cols = (const int*)  d_in[1];
    const float* vals = (const float*)d_in[2];
    const float4* user = (const float4*)d_in[3];
    const float4* item = (const float4*)d_in[4];
    float* out = (float*)d_out;

    float *bufA, *bufB;
    cudaGetSymbolAddress((void**)&bufA, g_bufA);
    cudaGetSymbolAddress((void**)&bufB, g_bufB);

    const int STREAM_BLK = 256;
    const int STREAM_GRID = (TOTAL_V4 + STREAM_BLK - 1) / STREAM_BLK;  // 18750
    const int SPMM_GRID = NNZ / 16;                                    // 600000

    // out = 0.25*e0; bufA = e0; bufB = 0
    init_kernel<<<STREAM_GRID, STREAM_BLK>>>(user, item, (float4*)out);

    // layer 1: bufB = S*bufA ; out += 0.25*bufB ; bufA = 0
    spmm_kernel<<<SPMM_GRID, 256>>>(rows, cols, vals, bufA, bufB);
    acc_zero_kernel<<<STREAM_GRID, STREAM_BLK>>>((float4*)out, (const float4*)bufB, (float4*)bufA);

    // layer 2: bufA = S*bufB ; out += 0.25*bufA ; bufB = 0
    spmm_kernel<<<SPMM_GRID, 256>>>(rows, cols, vals, bufB, bufA);
    acc_zero_kernel<<<STREAM_GRID, STREAM_BLK>>>((float4*)out, (const float4*)bufA, (float4*)bufB);

    // layer 3: bufB = S*bufA ; out += 0.25*bufB
    spmm_kernel<<<SPMM_GRID, 256>>>(rows, cols, vals, bufA, bufB);
    acc_final_kernel<<<STREAM_GRID, STREAM_BLK>>>((float4*)out, (const float4*)bufB);
}

// round 2
// speedup vs baseline: 1.2966x; 1.2966x over previous
#include <cuda_runtime.h>
#include <cuda_bf16.h>

#define N_USERS  100000
#define N_ITEMS  200000
#define N_NODES  300000
#define NNZ      9600000
#define DIM      64
#define TOTAL_F  (N_NODES * DIM)          // 19,200,000 floats
#define TOTAL_V4 (TOTAL_F / 4)            // 4,800,000 float4
#define USER_V4  (N_USERS * DIM / 4)      // 1,600,000 float4

// Ping-pong embedding buffers (alloc-free rule: __device__ globals)
__device__ float g_bufA[(size_t)TOTAL_F];
__device__ float g_bufB[(size_t)TOTAL_F];

// ---------------------------------------------------------------------------
// init: bufA = concat(user, item); out = 0.25*bufA; bufB = 0
// ---------------------------------------------------------------------------
__global__ void init_kernel(const float4* __restrict__ user,
                            const float4* __restrict__ item,
                            float4* __restrict__ out) {
    int i = blockIdx.x * blockDim.x + threadIdx.x;
    if (i >= TOTAL_V4) return;
    float4 v = (i < USER_V4) ? __ldg(&user[i]) : __ldg(&item[i - USER_V4]);
    float4* a = reinterpret_cast<float4*>(g_bufA);
    float4* b = reinterpret_cast<float4*>(g_bufB);
    a[i] = v;
    out[i] = make_float4(0.25f * v.x, 0.25f * v.y, 0.25f * v.z, 0.25f * v.w);
    b[i] = make_float4(0.f, 0.f, 0.f, 0.f);
}

// ---------------------------------------------------------------------------
// SpMM, 4 edges per thread for MLP:
//   y[rows[e]] += scale * vals[e] * x[cols[e]]
// Thread t: chunk c = t&15 (one float4 of the 64-dim row),
//           edge group g = t>>4 handles edges 4g..4g+3.
// NNZ/4 = 2,400,000 groups * 16 threads = 38.4M threads = 150,000 blocks.
// ---------------------------------------------------------------------------
__global__ void __launch_bounds__(256)
spmm_kernel(const int4*   __restrict__ rows4,
            const int4*   __restrict__ cols4,
            const float4* __restrict__ vals4,
            const float*  __restrict__ x,
            float*        __restrict__ y,
            float scale) {
    int t = blockIdx.x * blockDim.x + threadIdx.x;
    int g = t >> 4;          // edge group (4 edges)
    int c = t & 15;          // float4 chunk within the 64-dim row

    int4   r  = __ldg(&rows4[g]);
    int4   cl = __ldg(&cols4[g]);
    float4 vv = __ldg(&vals4[g]);

    // 4 independent gathers issued back-to-back (MLP = 4)
    float4 x0 = __ldg(reinterpret_cast<const float4*>(x + (size_t)cl.x * DIM) + c);
    float4 x1 = __ldg(reinterpret_cast<const float4*>(x + (size_t)cl.y * DIM) + c);
    float4 x2 = __ldg(reinterpret_cast<const float4*>(x + (size_t)cl.z * DIM) + c);
    float4 x3 = __ldg(reinterpret_cast<const float4*>(x + (size_t)cl.w * DIM) + c);

    float v0 = scale * vv.x, v1 = scale * vv.y, v2 = scale * vv.z, v3 = scale * vv.w;

    float* d0 = y + (size_t)r.x * DIM + (size_t)c * 4;
    float* d1 = y + (size_t)r.y * DIM + (size_t)c * 4;
    float* d2 = y + (size_t)r.z * DIM + (size_t)c * 4;
    float* d3 = y + (size_t)r.w * DIM + (size_t)c * 4;

    asm volatile("red.global.add.v4.f32 [%0], {%1, %2, %3, %4};"
                 :: "l"(d0), "f"(v0*x0.x), "f"(v0*x0.y), "f"(v0*x0.z), "f"(v0*x0.w) : "memory");
    asm volatile("red.global.add.v4.f32 [%0], {%1, %2, %3, %4};"
                 :: "l"(d1), "f"(v1*x1.x), "f"(v1*x1.y), "f"(v1*x1.z), "f"(v1*x1.w) : "memory");
    asm volatile("red.global.add.v4.f32 [%0], {%1, %2, %3, %4};"
                 :: "l"(d2), "f"(v2*x2.x), "f"(v2*x2.y), "f"(v2*x2.z), "f"(v2*x2.w) : "memory");
    asm volatile("red.global.add.v4.f32 [%0], {%1, %2, %3, %4};"
                 :: "l"(d3), "f"(v3*x3.x), "f"(v3*x3.y), "f"(v3*x3.z), "f"(v3*x3.w) : "memory");
}

// ---------------------------------------------------------------------------
// accumulate: out += 0.25 * src;  and zero the OTHER ping-pong buffer
// ---------------------------------------------------------------------------
__global__ void acc_zero_kernel(float4* __restrict__ out,
                                const float4* __restrict__ src,
                                float4* __restrict__ zbuf) {
    int i = blockIdx.x * blockDim.x + threadIdx.x;
    if (i >= TOTAL_V4) return;
    float4 s = __ldg(&src[i]);
    float4 o = out[i];
    o.x += 0.25f * s.x; o.y += 0.25f * s.y;
    o.z += 0.25f * s.z; o.w += 0.25f * s.w;
    out[i]  = o;
    zbuf[i] = make_float4(0.f, 0.f, 0.f, 0.f);
}

__global__ void acc_final_kernel(float4* __restrict__ out,
                                 const float4* __restrict__ src) {
    int i = blockIdx.x * blockDim.x + threadIdx.x;
    if (i >= TOTAL_V4) return;
    float4 s = __ldg(&src[i]);
    float4 o = out[i];
    o.x += 0.25f * s.x; o.y += 0.25f * s.y;
    o.z += 0.25f * s.z; o.w += 0.25f * s.w;
    out[i] = o;
}

// ---------------------------------------------------------------------------
extern "C" void kernel_launch(void* const* d_in, const int* in_sizes, int n_in,
                              void* d_out, int out_size) {
    const int4*   rows4 = (const int4*)  d_in[0];
    const int4*   cols4 = (const int4*)  d_in[1];
    const float4* vals4 = (const float4*)d_in[2];
    const float4* user  = (const float4*)d_in[3];
    const float4* item  = (const float4*)d_in[4];
    float* out = (float*)d_out;

    float *bufA, *bufB;
    cudaGetSymbolAddress((void**)&bufA, g_bufA);
    cudaGetSymbolAddress((void**)&bufB, g_bufB);

    const int STREAM_BLK = 256;
    const int STREAM_GRID = (TOTAL_V4 + STREAM_BLK - 1) / STREAM_BLK;  // 18750
    const int SPMM_GRID = (NNZ / 4) * 16 / 256;                        // 150000

    // out = 0.25*e0; bufA = e0; bufB = 0
    init_kernel<<<STREAM_GRID, STREAM_BLK>>>(user, item, (float4*)out);

    // layer 1: bufB = S*bufA ; out += 0.25*bufB ; bufA = 0
    spmm_kernel<<<SPMM_GRID, 256>>>(rows4, cols4, vals4, bufA, bufB, 1.0f);
    acc_zero_kernel<<<STREAM_GRID, STREAM_BLK>>>((float4*)out, (const float4*)bufB, (float4*)bufA);

    // layer 2: bufA = S*bufB ; out += 0.25*bufA  (no zeroing needed after)
    spmm_kernel<<<SPMM_GRID, 256>>>(rows4, cols4, vals4, bufB, bufA, 1.0f);
    acc_final_kernel<<<STREAM_GRID, STREAM_BLK>>>((float4*)out, (const float4*)bufA);

    // layer 3 fused epilogue: out += 0.25 * (S*bufA)  — RED directly into out
    spmm_kernel<<<SPMM_GRID, 256>>>(rows4, cols4, vals4, bufA, out, 0.25f);
}

// round 3
// speedup vs baseline: 1.3826x; 1.0663x over previous
#include <cuda_runtime.h>
#include <cuda_bf16.h>

#define N_USERS  100000
#define N_ITEMS  200000
#define N_NODES  300000
#define NNZ      9600000
#define DIM      64
#define TOTAL_F  (N_NODES * DIM)          // 19,200,000 floats
#define TOTAL_V4 (TOTAL_F / 4)            // 4,800,000 float4
#define USER_V4  (N_USERS * DIM / 4)      // 1,600,000 float4

// Ping-pong embedding buffers (alloc-free rule: __device__ globals)
__device__ float g_bufA[(size_t)TOTAL_F];
__device__ float g_bufB[(size_t)TOTAL_F];

// ---------------------------------------------------------------------------
// init: bufA = concat(user, item); out = 0.25*bufA; bufB = 0
// ---------------------------------------------------------------------------
__global__ void init_kernel(const float4* __restrict__ user,
                            const float4* __restrict__ item,
                            float4* __restrict__ out) {
    int i = blockIdx.x * blockDim.x + threadIdx.x;
    if (i >= TOTAL_V4) return;
    float4 v = (i < USER_V4) ? __ldg(&user[i]) : __ldg(&item[i - USER_V4]);
    float4* a = reinterpret_cast<float4*>(g_bufA);
    float4* b = reinterpret_cast<float4*>(g_bufB);
    a[i] = v;
    out[i] = make_float4(0.25f * v.x, 0.25f * v.y, 0.25f * v.z, 0.25f * v.w);
    b[i] = make_float4(0.f, 0.f, 0.f, 0.f);
}

// ---------------------------------------------------------------------------
// Gather load with L2 evict_last policy (pin gather source in L2).
// ---------------------------------------------------------------------------
__device__ __forceinline__ float4 ld_pin(const float4* p, unsigned long long pol) {
    float4 r;
    asm volatile("ld.global.nc.L2::cache_hint.v4.f32 {%0,%1,%2,%3}, [%4], %5;"
                 : "=f"(r.x), "=f"(r.y), "=f"(r.z), "=f"(r.w)
                 : "l"(p), "l"(pol));
    return r;
}

__device__ __forceinline__ void red_v4(float* d, float4 m) {
    asm volatile("red.global.add.v4.f32 [%0], {%1, %2, %3, %4};"
                 :: "l"(d), "f"(m.x), "f"(m.y), "f"(m.z), "f"(m.w) : "memory");
}

// ---------------------------------------------------------------------------
// SpMM, 8 edges per thread:
//   y[rows[e]] += scale * vals[e] * x[cols[e]]
// Thread t: chunk c = t&15 (one float4 of the 64-dim row),
//           group g = t>>4 handles edges 8g..8g+7.
// Edge stream loaded with .cs (evict-first); x gathers pinned evict_last.
// NNZ/8 = 1,200,000 groups * 16 threads / 256 = 75,000 blocks (no tail).
// ---------------------------------------------------------------------------
__global__ void __launch_bounds__(256)
spmm_kernel(const int4*   __restrict__ rows4,
            const int4*   __restrict__ cols4,
            const float4* __restrict__ vals4,
            const float*  __restrict__ x,
            float*        __restrict__ y,
            float scale) {
    int t = blockIdx.x * blockDim.x + threadIdx.x;
    int g = t >> 4;          // group of 8 edges
    int c = t & 15;          // float4 chunk within the 64-dim row

    unsigned long long pol;
    asm("createpolicy.fractional.L2::evict_last.b64 %0, 1.0;" : "=l"(pol));

    int4   ra = __ldcs(&rows4[2*g]),   rb = __ldcs(&rows4[2*g+1]);
    int4   ca = __ldcs(&cols4[2*g]),   cb = __ldcs(&cols4[2*g+1]);
    float4 va = __ldcs(&vals4[2*g]),   vb = __ldcs(&vals4[2*g+1]);

    const float4* xb = reinterpret_cast<const float4*>(x);

    // 8 independent gathers back-to-back (MLP = 8), pinned in L2
    float4 x0 = ld_pin(xb + (size_t)ca.x * 16 + c, pol);
    float4 x1 = ld_pin(xb + (size_t)ca.y * 16 + c, pol);
    float4 x2 = ld_pin(xb + (size_t)ca.z * 16 + c, pol);
    float4 x3 = ld_pin(xb + (size_t)ca.w * 16 + c, pol);
    float4 x4 = ld_pin(xb + (size_t)cb.x * 16 + c, pol);
    float4 x5 = ld_pin(xb + (size_t)cb.y * 16 + c, pol);
    float4 x6 = ld_pin(xb + (size_t)cb.z * 16 + c, pol);
    float4 x7 = ld_pin(xb + (size_t)cb.w * 16 + c, pol);

    float v0 = scale*va.x, v1 = scale*va.y, v2 = scale*va.z, v3 = scale*va.w;
    float v4 = scale*vb.x, v5 = scale*vb.y, v6 = scale*vb.z, v7 = scale*vb.w;

    size_t co = (size_t)c * 4;
    red_v4(y + (size_t)ra.x * DIM + co, make_float4(v0*x0.x, v0*x0.y, v0*x0.z, v0*x0.w));
    red_v4(y + (size_t)ra.y * DIM + co, make_float4(v1*x1.x, v1*x1.y, v1*x1.z, v1*x1.w));
    red_v4(y + (size_t)ra.z * DIM + co, make_float4(v2*x2.x, v2*x2.y, v2*x2.z, v2*x2.w));
    red_v4(y + (size_t)ra.w * DIM + co, make_float4(v3*x3.x, v3*x3.y, v3*x3.z, v3*x3.w));
    red_v4(y + (size_t)rb.x * DIM + co, make_float4(v4*x4.x, v4*x4.y, v4*x4.z, v4*x4.w));
    red_v4(y + (size_t)rb.y * DIM + co, make_float4(v5*x5.x, v5*x5.y, v5*x5.z, v5*x5.w));
    red_v4(y + (size_t)rb.z * DIM + co, make_float4(v6*x6.x, v6*x6.y, v6*x6.z, v6*x6.w));
    red_v4(y + (size_t)rb.w * DIM + co, make_float4(v7*x7.x, v7*x7.y, v7*x7.z, v7*x7.w));
}

// ---------------------------------------------------------------------------
// accumulate: out += 0.25 * src;  and zero the OTHER ping-pong buffer
// ---------------------------------------------------------------------------
__global__ void acc_zero_kernel(float4* __restrict__ out,
                                const float4* __restrict__ src,
                                float4* __restrict__ zbuf) {
    int i = blockIdx.x * blockDim.x + threadIdx.x;
    if (i >= TOTAL_V4) return;
    float4 s = __ldg(&src[i]);
    float4 o = out[i];
    o.x += 0.25f * s.x; o.y += 0.25f * s.y;
    o.z += 0.25f * s.z; o.w += 0.25f * s.w;
    out[i]  = o;
    zbuf[i] = make_float4(0.f, 0.f, 0.f, 0.f);
}

__global__ void acc_final_kernel(float4* __restrict__ out,
                                 const float4* __restrict__ src) {
    int i = blockIdx.x * blockDim.x + threadIdx.x;
    if (i >= TOTAL_V4) return;
    float4 s = __ldg(&src[i]);
    float4 o = out[i];
    o.x += 0.25f * s.x; o.y += 0.25f * s.y;
    o.z += 0.25f * s.z; o.w += 0.25f * s.w;
    out[i] = o;
}

// ---------------------------------------------------------------------------
extern "C" void kernel_launch(void* const* d_in, const int* in_sizes, int n_in,
                              void* d_out, int out_size) {
    const int4*   rows4 = (const int4*)  d_in[0];
    const int4*   cols4 = (const int4*)  d_in[1];
    const float4* vals4 = (const float4*)d_in[2];
    const float4* user  = (const float4*)d_in[3];
    const float4* item  = (const float4*)d_in[4];
    float* out = (float*)d_out;

    float *bufA, *bufB;
    cudaGetSymbolAddress((void**)&bufA, g_bufA);
    cudaGetSymbolAddress((void**)&bufB, g_bufB);

    const int STREAM_BLK = 256;
    const int STREAM_GRID = (TOTAL_V4 + STREAM_BLK - 1) / STREAM_BLK;  // 18750
    const int SPMM_GRID = (NNZ / 8) * 16 / 256;                        // 75000

    // out = 0.25*e0; bufA = e0; bufB = 0
    init_kernel<<<STREAM_GRID, STREAM_BLK>>>(user, item, (float4*)out);

    // layer 1: bufB = S*bufA ; out += 0.25*bufB ; bufA = 0
    spmm_kernel<<<SPMM_GRID, 256>>>(rows4, cols4, vals4, bufA, bufB, 1.0f);
    acc_zero_kernel<<<STREAM_GRID, STREAM_BLK>>>((float4*)out, (const float4*)bufB, (float4*)bufA);

    // layer 2: bufA = S*bufB ; out += 0.25*bufA
    spmm_kernel<<<SPMM_GRID, 256>>>(rows4, cols4, vals4, bufB, bufA, 1.0f);
    acc_final_kernel<<<STREAM_GRID, STREAM_BLK>>>((float4*)out, (const float4*)bufA);

    // layer 3 fused epilogue: out += 0.25 * (S*bufA)  — RED directly into out
    spmm_kernel<<<SPMM_GRID, 256>>>(rows4, cols4, vals4, bufA, out, 0.25f);
}

// round 9
// speedup vs baseline: 1.7301x; 1.2513x over previous
#include <cuda_runtime.h>
#include <cuda_fp16.h>

#define N_USERS  100000
#define N_ITEMS  200000
#define N_NODES  300000
#define NNZ      9600000
#define DIM      64
#define TOTAL_F  (N_NODES * DIM)          // 19,200,000 floats
#define TOTAL_V4 (TOTAL_F / 4)            // 4,800,000 float4
#define USER_V4  (N_USERS * DIM / 4)      // 1,600,000 float4

// Scratch (alloc-free rule: __device__ globals)
__device__ float  g_y[(size_t)TOTAL_F];   // fp32 scatter target, reused every layer (76.8 MB)
__device__ __half g_h[(size_t)TOTAL_F];   // fp16 gather source shadow (38.4 MB)

// ---------------------------------------------------------------------------
// helpers
// ---------------------------------------------------------------------------
__device__ __forceinline__ unsigned long long ld_pin64(const void* p, unsigned long long pol) {
    unsigned long long r;
    asm volatile("ld.global.nc.L2::cache_hint.b64 %0, [%1], %2;"
                 : "=l"(r) : "l"(p), "l"(pol));
    return r;
}

__device__ __forceinline__ void red_v4(float* d, float4 m, unsigned long long pol) {
    asm volatile("red.global.add.L2::cache_hint.v4.f32 [%0], {%1, %2, %3, %4}, %5;"
                 :: "l"(d), "f"(m.x), "f"(m.y), "f"(m.z), "f"(m.w), "l"(pol) : "memory");
}

__device__ __forceinline__ unsigned long long pack_half4(float4 v) {
    __half2 p0 = __floats2half2_rn(v.x, v.y);
    __half2 p1 = __floats2half2_rn(v.z, v.w);
    unsigned long long r;
    asm("mov.b64 %0, {%1, %2};" : "=l"(r)
        : "r"(*(unsigned*)&p0), "r"(*(unsigned*)&p1));
    return r;
}

__device__ __forceinline__ float4 unpack_scaled(unsigned long long q, float v) {
    unsigned lo, hi;
    asm("mov.b64 {%0, %1}, %2;" : "=r"(lo), "=r"(hi) : "l"(q));
    float2 a = __half22float2(*(__half2*)&lo);
    float2 b = __half22float2(*(__half2*)&hi);
    return make_float4(v*a.x, v*a.y, v*b.x, v*b.y);
}

// ---------------------------------------------------------------------------
// init: h = half(e0); out = 0.25*e0; y = 0
// ---------------------------------------------------------------------------
__global__ void init_kernel(const float4* __restrict__ user,
                            const float4* __restrict__ item,
                            float4* __restrict__ out) {
    int i = blockIdx.x * blockDim.x + threadIdx.x;
    if (i >= TOTAL_V4) return;
    float4 v = (i < USER_V4) ? __ldg(&user[i]) : __ldg(&item[i - USER_V4]);
    out[i] = make_float4(0.25f*v.x, 0.25f*v.y, 0.25f*v.z, 0.25f*v.w);
    reinterpret_cast<unsigned long long*>(g_h)[i] = pack_half4(v);
    reinterpret_cast<float4*>(g_y)[i] = make_float4(0.f, 0.f, 0.f, 0.f);
}

// ---------------------------------------------------------------------------
// SpMM, 8 edges per thread, fp16 gather (8B), fp32 v4 RED scatter:
//   y[rows[e]] += scale * vals[e] * half2float(h[cols[e]])
// Thread t: chunk c = t&15, group g = t>>4 handles edges 8g..8g+7.
// NNZ/8 * 16 / 256 = 75,000 blocks, no tail.
// ---------------------------------------------------------------------------
__global__ void __launch_bounds__(256)
spmm_kernel(const int4*   __restrict__ rows4,
            const int4*   __restrict__ cols4,
            const float4* __restrict__ vals4,
            const __half* __restrict__ x,
            float*        __restrict__ y,
            float scale) {
    int t = blockIdx.x * blockDim.x + threadIdx.x;
    int g = t >> 4;
    int c = t & 15;

    unsigned long long pol;
    asm("createpolicy.fractional.L2::evict_last.b64 %0, 1.0;" : "=l"(pol));

    int4   ra = __ldcs(&rows4[2*g]), rb = __ldcs(&rows4[2*g+1]);
    int4   ca = __ldcs(&cols4[2*g]), cb = __ldcs(&cols4[2*g+1]);
    float4 va = __ldcs(&vals4[2*g]), vb = __ldcs(&vals4[2*g+1]);

    const char* xb = reinterpret_cast<const char*>(x);
    size_t co8 = (size_t)c * 8;      // byte offset of this chunk in an fp16 row (128B)

    // 8 independent 8B gathers (MLP = 8), pinned evict_last
    unsigned long long q0 = ld_pin64(xb + (size_t)ca.x*128 + co8, pol);
    unsigned long long q1 = ld_pin64(xb + (size_t)ca.y*128 + co8, pol);
    unsigned long long q2 = ld_pin64(xb + (size_t)ca.z*128 + co8, pol);
    unsigned long long q3 = ld_pin64(xb + (size_t)ca.w*128 + co8, pol);
    unsigned long long q4 = ld_pin64(xb + (size_t)cb.x*128 + co8, pol);
    unsigned long long q5 = ld_pin64(xb + (size_t)cb.y*128 + co8, pol);
    unsigned long long q6 = ld_pin64(xb + (size_t)cb.z*128 + co8, pol);
    unsigned long long q7 = ld_pin64(xb + (size_t)cb.w*128 + co8, pol);

    size_t co = (size_t)c * 4;
    red_v4(y + (size_t)ra.x*DIM + co, unpack_scaled(q0, scale*va.x), pol);
    red_v4(y + (size_t)ra.y*DIM + co, unpack_scaled(q1, scale*va.y), pol);
    red_v4(y + (size_t)ra.z*DIM + co, unpack_scaled(q2, scale*va.z), pol);
    red_v4(y + (size_t)ra.w*DIM + co, unpack_scaled(q3, scale*va.w), pol);
    red_v4(y + (size_t)rb.x*DIM + co, unpack_scaled(q4, scale*vb.x), pol);
    red_v4(y + (size_t)rb.y*DIM + co, unpack_scaled(q5, scale*vb.y), pol);
    red_v4(y + (size_t)rb.z*DIM + co, unpack_scaled(q6, scale*vb.z), pol);
    red_v4(y + (size_t)rb.w*DIM + co, unpack_scaled(q7, scale*vb.w), pol);
}

// ---------------------------------------------------------------------------
// acc: out += 0.25*y; h = half(y); y = 0   (prepares next layer)
// ---------------------------------------------------------------------------
__global__ void acc_kernel(float4* __restrict__ out) {
    int i = blockIdx.x * blockDim.x + threadIdx.x;
    if (i >= TOTAL_V4) return;
    float4* y4 = reinterpret_cast<float4*>(g_y);
    float4 s = y4[i];
    float4 o = out[i];
    o.x += 0.25f*s.x; o.y += 0.25f*s.y; o.z += 0.25f*s.z; o.w += 0.25f*s.w;
    out[i] = o;
    reinterpret_cast<unsigned long long*>(g_h)[i] = pack_half4(s);
    y4[i] = make_float4(0.f, 0.f, 0.f, 0.f);
}

// ---------------------------------------------------------------------------
extern "C" void kernel_launch(void* const* d_in, const int* in_sizes, int n_in,
                              void* d_out, int out_size) {
    const int4*   rows4 = (const int4*)  d_in[0];
    const int4*   cols4 = (const int4*)  d_in[1];
    const float4* vals4 = (const float4*)d_in[2];
    const float4* user  = (const float4*)d_in[3];
    const float4* item  = (const float4*)d_in[4];
    float* out = (float*)d_out;

    float  *y;  cudaGetSymbolAddress((void**)&y,  g_y);
    __half *h;  cudaGetSymbolAddress((void**)&h,  g_h);

    const int STREAM_BLK = 256;
    const int STREAM_GRID = (TOTAL_V4 + STREAM_BLK - 1) / STREAM_BLK;  // 18750
    const int SPMM_GRID = (NNZ / 8) * 16 / 256;                        // 75000

    // h = half(e0); out = 0.25*e0; y = 0
    init_kernel<<<STREAM_GRID, STREAM_BLK>>>(user, item, (float4*)out);

    // layer 1: y = S*h ; out += 0.25*y ; h = half(y) ; y = 0
    spmm_kernel<<<SPMM_GRID, 256>>>(rows4, cols4, vals4, h, y, 1.0f);
    acc_kernel<<<STREAM_GRID, STREAM_BLK>>>((float4*)out);

    // layer 2: y = S*h ; out += 0.25*y ; h = half(y) ; y = 0
    spmm_kernel<<<SPMM_GRID, 256>>>(rows4, cols4, vals4, h, y, 1.0f);
    acc_kernel<<<STREAM_GRID, STREAM_BLK>>>((float4*)out);

    // layer 3 fused epilogue: out += 0.25 * (S*h) — RED directly into out
    spmm_kernel<<<SPMM_GRID, 256>>>(rows4, cols4, vals4, h, out, 0.25f);
}

// round 11
// speedup vs baseline: 3.0636x; 1.7707x over previous
#include <cuda_runtime.h>
#include <cuda_fp16.h>

#define N_USERS  100000
#define N_ITEMS  200000
#define N_NODES  300000
#define NNZ      9600000
#define DIM      64
#define TOTAL_F  (N_NODES * DIM)          // 19,200,000 halves per buffer
#define TOTAL_V4 (TOTAL_F / 4)            // 4,800,000 groups of 4
#define USER_V4  (N_USERS * DIM / 4)      // 1,600,000

// Ping-pong fp16 embedding buffers (alloc-free rule: __device__ globals), 38.4 MB each
__device__ __half g_A[(size_t)TOTAL_F];
__device__ __half g_B[(size_t)TOTAL_F];

// ---------------------------------------------------------------------------
// helpers
// ---------------------------------------------------------------------------
__device__ __forceinline__ uint4 ld_pin16(const void* p, unsigned long long pol) {
    uint4 r;
    asm volatile("ld.global.nc.L2::cache_hint.v4.b32 {%0,%1,%2,%3}, [%4], %5;"
                 : "=r"(r.x), "=r"(r.y), "=r"(r.z), "=r"(r.w)
                 : "l"(p), "l"(pol));
    return r;
}

// 16B half-precision vector reduction: adds 8 halves at [d]
__device__ __forceinline__ void red_h8(void* d, uint4 m, unsigned long long pol) {
    asm volatile("red.global.add.noftz.L2::cache_hint.v4.f16x2 [%0], {%1,%2,%3,%4}, %5;"
                 :: "l"(d), "r"(m.x), "r"(m.y), "r"(m.z), "r"(m.w), "l"(pol) : "memory");
}

// multiply 8 halves (packed in uint4) by broadcast half2
__device__ __forceinline__ uint4 mul8h(uint4 q, __half2 v) {
    uint4 r;
    __half2 h;
    h = __hmul2(*(__half2*)&q.x, v); r.x = *(unsigned*)&h;
    h = __hmul2(*(__half2*)&q.y, v); r.y = *(unsigned*)&h;
    h = __hmul2(*(__half2*)&q.z, v); r.z = *(unsigned*)&h;
    h = __hmul2(*(__half2*)&q.w, v); r.w = *(unsigned*)&h;
    return r;
}

__device__ __forceinline__ unsigned long long pack_half4(float4 v) {
    __half2 p0 = __floats2half2_rn(v.x, v.y);
    __half2 p1 = __floats2half2_rn(v.z, v.w);
    unsigned long long r;
    asm("mov.b64 %0, {%1, %2};" : "=l"(r)
        : "r"(*(unsigned*)&p0), "r"(*(unsigned*)&p1));
    return r;
}

// ---------------------------------------------------------------------------
// init: A = half(e0); out = 0.25*e0; B = 0
// ---------------------------------------------------------------------------
__global__ void init_kernel(const float4* __restrict__ user,
                            const float4* __restrict__ item,
                            float4* __restrict__ out) {
    int i = blockIdx.x * blockDim.x + threadIdx.x;
    if (i >= TOTAL_V4) return;
    float4 v = (i < USER_V4) ? __ldg(&user[i]) : __ldg(&item[i - USER_V4]);
    out[i] = make_float4(0.25f*v.x, 0.25f*v.y, 0.25f*v.z, 0.25f*v.w);
    reinterpret_cast<unsigned long long*>(g_A)[i] = pack_half4(v);
    reinterpret_cast<unsigned long long*>(g_B)[i] = 0ull;
}

// ---------------------------------------------------------------------------
// SpMM, fully fp16, 8 lanes per edge, 8 edges per thread:
//   y[rows[e]] += vals[e] * x[cols[e]]     (x, y fp16, 128B rows)
// Thread t: chunk c = t&7 (16B = 8 halves), group g = t>>3 (edges 8g..8g+7).
// Threads = NNZ  ->  37,500 blocks of 256, no tail.
// Per edge: ONE 16B gather line + ONE 16B RED line per lane-group.
// ---------------------------------------------------------------------------
__global__ void __launch_bounds__(256)
spmm_kernel(const int4*   __restrict__ rows4,
            const int4*   __restrict__ cols4,
            const float4* __restrict__ vals4,
            const __half* __restrict__ x,
            __half*       __restrict__ y) {
    int t = blockIdx.x * blockDim.x + threadIdx.x;
    int g = t >> 3;
    int c = t & 7;

    unsigned long long pol;
    asm("createpolicy.fractional.L2::evict_last.b64 %0, 1.0;" : "=l"(pol));

    int4   ra = __ldcs(&rows4[2*g]), rb = __ldcs(&rows4[2*g+1]);
    int4   ca = __ldcs(&cols4[2*g]), cb = __ldcs(&cols4[2*g+1]);
    float4 va = __ldcs(&vals4[2*g]), vb = __ldcs(&vals4[2*g+1]);

    const char* xb = reinterpret_cast<const char*>(x);
    char*       yb = reinterpret_cast<char*>(y);
    size_t co = (size_t)c * 16;     // byte offset of this 16B chunk in a 128B row

    // 8 independent 16B gathers (MLP = 8), pinned evict_last
    uint4 q0 = ld_pin16(xb + (size_t)ca.x*128 + co, pol);
    uint4 q1 = ld_pin16(xb + (size_t)ca.y*128 + co, pol);
    uint4 q2 = ld_pin16(xb + (size_t)ca.z*128 + co, pol);
    uint4 q3 = ld_pin16(xb + (size_t)ca.w*128 + co, pol);
    uint4 q4 = ld_pin16(xb + (size_t)cb.x*128 + co, pol);
    uint4 q5 = ld_pin16(xb + (size_t)cb.y*128 + co, pol);
    uint4 q6 = ld_pin16(xb + (size_t)cb.z*128 + co, pol);
    uint4 q7 = ld_pin16(xb + (size_t)cb.w*128 + co, pol);

    red_h8(yb + (size_t)ra.x*128 + co, mul8h(q0, __float2half2_rn(va.x)), pol);
    red_h8(yb + (size_t)ra.y*128 + co, mul8h(q1, __float2half2_rn(va.y)), pol);
    red_h8(yb + (size_t)ra.z*128 + co, mul8h(q2, __float2half2_rn(va.z)), pol);
    red_h8(yb + (size_t)ra.w*128 + co, mul8h(q3, __float2half2_rn(va.w)), pol);
    red_h8(yb + (size_t)rb.x*128 + co, mul8h(q4, __float2half2_rn(vb.x)), pol);
    red_h8(yb + (size_t)rb.y*128 + co, mul8h(q5, __float2half2_rn(vb.y)), pol);
    red_h8(yb + (size_t)rb.z*128 + co, mul8h(q6, __float2half2_rn(vb.z)), pol);
    red_h8(yb + (size_t)rb.w*128 + co, mul8h(q7, __float2half2_rn(vb.w)), pol);
}

// ---------------------------------------------------------------------------
// acc: out += 0.25 * src(fp16);  optionally zero the other ping-pong buffer
// ---------------------------------------------------------------------------
__device__ __forceinline__ void acc_body(float4* out, const unsigned long long* src, int i) {
    unsigned long long q = __ldg(&src[i]);
    unsigned lo, hi;
    asm("mov.b64 {%0, %1}, %2;" : "=r"(lo), "=r"(hi) : "l"(q));
    float2 a = __half22float2(*(__half2*)&lo);
    float2 b = __half22float2(*(__half2*)&hi);
    float4 o = out[i];
    o.x += 0.25f*a.x; o.y += 0.25f*a.y; o.z += 0.25f*b.x; o.w += 0.25f*b.y;
    out[i] = o;
}

__global__ void acc_zero_kernel(float4* __restrict__ out,
                                const unsigned long long* __restrict__ src,
                                unsigned long long* __restrict__ zbuf) {
    int i = blockIdx.x * blockDim.x + threadIdx.x;
    if (i >= TOTAL_V4) return;
    acc_body(out, src, i);
    zbuf[i] = 0ull;
}

__global__ void acc_final_kernel(float4* __restrict__ out,
                                 const unsigned long long* __restrict__ src) {
    int i = blockIdx.x * blockDim.x + threadIdx.x;
    if (i >= TOTAL_V4) return;
    acc_body(out, src, i);
}

// ---------------------------------------------------------------------------
extern "C" void kernel_launch(void* const* d_in, const int* in_sizes, int n_in,
                              void* d_out, int out_size) {
    const int4*   rows4 = (const int4*)  d_in[0];
    const int4*   cols4 = (const int4*)  d_in[1];
    const float4* vals4 = (const float4*)d_in[2];
    const float4* user  = (const float4*)d_in[3];
    const float4* item  = (const float4*)d_in[4];
    float* out = (float*)d_out;

    __half *A, *B;
    cudaGetSymbolAddress((void**)&A, g_A);
    cudaGetSymbolAddress((void**)&B, g_B);

    const int STREAM_BLK = 256;
    const int STREAM_GRID = (TOTAL_V4 + STREAM_BLK - 1) / STREAM_BLK;  // 18750
    const int SPMM_GRID = NNZ / 256;                                   // 37500

    // A = half(e0); out = 0.25*e0; B = 0
    init_kernel<<<STREAM_GRID, STREAM_BLK>>>(user, item, (float4*)out);

    // layer 1: B = S*A ; out += 0.25*B ; A = 0
    spmm_kernel<<<SPMM_GRID, 256>>>(rows4, cols4, vals4, A, B);
    acc_zero_kernel<<<STREAM_GRID, STREAM_BLK>>>((float4*)out,
        (const unsigned long long*)B, (unsigned long long*)A);

    // layer 2: A = S*B ; out += 0.25*A ; B = 0
    spmm_kernel<<<SPMM_GRID, 256>>>(rows4, cols4, vals4, B, A);
    acc_zero_kernel<<<STREAM_GRID, STREAM_BLK>>>((float4*)out,
        (const unsigned long long*)A, (unsigned long long*)B);

    // layer 3: B = S*A ; out += 0.25*B
    spmm_kernel<<<SPMM_GRID, 256>>>(rows4, cols4, vals4, A, B);
    acc_final_kernel<<<STREAM_GRID, STREAM_BLK>>>((float4*)out,
        (const unsigned long long*)B);
}